// round 13
// baseline (speedup 1.0000x reference)
#include <cuda_runtime.h>
#include <cstdint>

#define NB 64
#define NO 10
#define NI 8000
#define ND 16
#define NE 8

#define ITILE 2
#define NTHR 256                 // 2 blocks/SM, independent pipelines
#define NBLK 296                 // total blocks (148 pairs)
#define NPAIR 148                // i-stride in stages
#define NSTAGES (NI / ITILE)     // 4000 stages of 2 i's
#define STEPI (NPAIR * ITILE)    // i0 advance per grid-stride step = 296

#define NWITEM (ITILE * NO * 32) // 640 W float4 per stage
#define NXITEM (ITILE * 32 * 2)  // 128 x float4 per stage (32-batch half)
#define WBUFB (NWITEM * 16)      // 10240 B per W buffer
#define XBUFB (NXITEM * 16)      // 2048 B per x buffer

// Scratch (no allocation allowed). g_s zeroed by the fused squash each pass,
// g_ticket reset by the last block -> graph replays are deterministic.
__device__ float g_s[NB * NO * ND] = {};
__device__ float g_v[NB * NO * ND] = {};
__device__ float g_vsum[NB * NO * ND] = {};
__device__ unsigned int g_ticket = 0;

// ---- f32x2 packed math (sm_10x; ptxas won't auto-fuse, must be PTX) ----
__device__ __forceinline__ unsigned long long f2mul(unsigned long long a, unsigned long long b) {
    unsigned long long d;
    asm("mul.rn.f32x2 %0, %1, %2;" : "=l"(d) : "l"(a), "l"(b));
    return d;
}
__device__ __forceinline__ unsigned long long f2fma(unsigned long long a, unsigned long long b, unsigned long long c) {
    unsigned long long d;
    asm("fma.rn.f32x2 %0, %1, %2, %3;" : "=l"(d) : "l"(a), "l"(b), "l"(c));
    return d;
}
__device__ __forceinline__ float f2hadd(unsigned long long a) {
    float lo, hi;
    asm("mov.b64 {%0, %1}, %2;" : "=f"(lo), "=f"(hi) : "l"(a));
    return lo + hi;
}

// ---- cp.async (LDGSTS) helpers ----
__device__ __forceinline__ void cp16(uint32_t dst, const void* src) {
    asm volatile("cp.async.ca.shared.global [%0], [%1], 16;" :: "r"(dst), "l"(src));
}
__device__ __forceinline__ void cp_commit() { asm volatile("cp.async.commit_group;"); }
template <int N>
__device__ __forceinline__ void cp_wait() { asm volatile("cp.async.wait_group %0;" :: "n"(N)); }
__device__ __forceinline__ uint32_t sptr(const void* p) {
    return (uint32_t)__cvta_generic_to_shared(p);
}

// ---- staging: 256 threads stage 640 W f4 + 128 x f4 per stage (3 cp16 each)
// cp A: W item tid; cp B: W item tid+256;
// cp C: tid<128 -> W item tid+512, else x item tid-128 (this block's 32 b's).
struct Stager {
    const float4 *sA, *sB, *sC;
    uint32_t dA, dB, dC, bufC;
    int stC;

    __device__ __forceinline__ void initW(int t, int i00, const float4* Wf4,
                                          uint32_t swbase,
                                          const float4*& src, uint32_t& dst) {
        int j  = t / (NO * 32);
        int r  = t - j * (NO * 32);
        int o  = r >> 5;
        int qg = r & 31;                       // global: d*2 + e4
        int qs = ((qg & 1) << 4) | (qg >> 1);  // shared: e4*16 + d
        src = Wf4 + ((size_t)o * NI + i00 + j) * 32 + qg;
        dst = swbase + (uint32_t)((j * NO + o) * 32 + qs) * 16u;
    }

    __device__ __forceinline__ void init(int tid, int bhalf, int i00,
                                         const float4* Wf4, const float4* xf4,
                                         uint32_t swbase, uint32_t sxbase) {
        initW(tid,       i00, Wf4, swbase, sA, dA);
        initW(tid + 256, i00, Wf4, swbase, sB, dB);
        if (tid < 128) {                       // W item tid+512
            initW(tid + 512, i00, Wf4, swbase, sC, dC);
            stC  = 32 * STEPI;
            bufC = WBUFB;
        } else {                               // x item v in [0,128)
            int v  = tid - 128;
            int j  = v >> 6;
            int rr = v & 63;
            int bl = rr >> 1;                  // block-local batch 0..31
            int q  = rr & 1;
            sC  = xf4 + ((size_t)(bhalf * 32 + bl) * NI + i00 + j) * 2 + q;
            dC  = sxbase + (uint32_t)((j * 32 + bl) * 2 + q) * 16u;
            stC  = 2 * STEPI;
            bufC = XBUFB;
        }
    }
    __device__ __forceinline__ void issue(int ib) {
        cp16(dA + (uint32_t)ib * WBUFB, sA);  sA += 32 * STEPI;
        cp16(dB + (uint32_t)ib * WBUFB, sB);  sB += 32 * STEPI;
        cp16(dC + (uint32_t)ib * bufC,  sC);  sC += stC;
        cp_commit();
    }
};

// ---- fused squash epilogue (last of all 296 blocks) ----
template <int ITER>
__device__ __forceinline__ void squash_epilogue(int tid, float* __restrict__ out)
{
    __threadfence();
    __shared__ unsigned int lastFlag;
    if (tid == 0)
        lastFlag = (atomicAdd(&g_ticket, 1u) == (unsigned)(NBLK - 1)) ? 1u : 0u;
    __syncthreads();
    if (!lastFlag) return;
    __threadfence();  // acquire: all other blocks' atomics are visible

    const float prescale = (ITER == 0) ? 0.1f : 1.0f;
    for (int k = 0; k < (NB * NO * ND) / NTHR; k++) {
        int idx = k * NTHR + tid;            // idx & 15 == d-lane
        float val = g_s[idx] * prescale;
        g_s[idx] = 0.f;
        float n2 = val * val;
        n2 += __shfl_xor_sync(0xffffffffu, n2, 8, 16);
        n2 += __shfl_xor_sync(0xffffffffu, n2, 4, 16);
        n2 += __shfl_xor_sync(0xffffffffu, n2, 2, 16);
        n2 += __shfl_xor_sync(0xffffffffu, n2, 1, 16);
        float norm  = sqrtf(n2);
        float scale = n2 / ((1.f + n2) * (norm + 1e-8f));
        float v = scale * val;
        if (ITER == 0)      { g_v[idx] = v; g_vsum[idx] = v; }
        else if (ITER == 1) { g_v[idx] = v; g_vsum[idx] += v; }
        else                { out[idx] = v; }
    }
    if (tid == 0) g_ticket = 0;  // reset for next pass / next graph replay
}

// ============ PASS 0: (4 batch, 5 o) per thread, 256-thr half-block ============
__global__ void __launch_bounds__(NTHR, 2)
pass0_kernel(const float* __restrict__ xg, const float* __restrict__ Wg,
             float* __restrict__ out)
{
    __shared__ float4 shW[3][NWITEM];  // 3 x 10 KB
    __shared__ float4 shx[3][NXITEM];  // 3 x 2 KB

    const int tid  = threadIdx.x;
    const int bhalf = blockIdx.x & 1;       // batch half: 0 -> b 0..31, 1 -> 32..63
    const int st0   = blockIdx.x >> 1;      // stage start (pairs share i-range)

    const int lane = tid & 15;              // d
    const int grp  = tid >> 4;              // 0..15
    const int ql   = grp >> 1;              // local quad 0..7 -> local b 4ql..4ql+3
    const int ob   = (grp & 1) * 5;         // o-half base: 0 or 5
    const int bg0  = bhalf * 32 + ql * 4;   // global batch base

    unsigned long long accp[4][5];
    #pragma unroll
    for (int bb = 0; bb < 4; bb++)
        #pragma unroll
        for (int o = 0; o < 5; o++) accp[bb][o] = 0ull;

    const float4* Wf4 = (const float4*)Wg;
    const float4* xf4 = (const float4*)xg;

    Stager sg;
    sg.init(tid, bhalf, st0 * ITILE, Wf4, xf4, sptr(&shW[0][0]), sptr(&shx[0][0]));

    sg.issue(0);
    if (st0 + NPAIR < NSTAGES) sg.issue(1); else cp_commit();

    int parity = 0, inext = 2;
    for (int st = st0; st < NSTAGES; st += NPAIR) {
        cp_wait<1>();
        __syncthreads();
        if (st + 2 * NPAIR < NSTAGES) sg.issue(inext); else cp_commit();
        inext = (inext + 1 == 3) ? 0 : inext + 1;

        const ulonglong2* shWc = reinterpret_cast<const ulonglong2*>(shW[parity]);
        const ulonglong2* shxc = reinterpret_cast<const ulonglong2*>(shx[parity]);

        #pragma unroll
        for (int j = 0; j < ITILE; j++) {
            ulonglong2 xa[4], xb[4];
            #pragma unroll
            for (int bb = 0; bb < 4; bb++) {
                xa[bb] = shxc[(j * 32 + ql * 4 + bb) * 2 + 0];  // e0..3
                xb[bb] = shxc[(j * 32 + ql * 4 + bb) * 2 + 1];  // e4..7
            }
            #pragma unroll
            for (int o = 0; o < 5; o++) {
                const int og = ob + o;
                ulonglong2 wa = shWc[(j * NO + og) * 32 + lane];       // e0..3
                ulonglong2 wb = shWc[(j * NO + og) * 32 + 16 + lane];  // e4..7
                #pragma unroll
                for (int bb = 0; bb < 4; bb++) {
                    accp[bb][o] = f2fma(wa.x, xa[bb].x, accp[bb][o]);
                    accp[bb][o] = f2fma(wa.y, xa[bb].y, accp[bb][o]);
                    accp[bb][o] = f2fma(wb.x, xb[bb].x, accp[bb][o]);
                    accp[bb][o] = f2fma(wb.y, xb[bb].y, accp[bb][o]);
                }
            }
        }
        parity = (parity + 1 == 3) ? 0 : parity + 1;
    }

    #pragma unroll
    for (int bb = 0; bb < 4; bb++)
        #pragma unroll
        for (int o = 0; o < 5; o++)
            atomicAdd(&g_s[((bg0 + bb) * NO + ob + o) * ND + lane],
                      f2hadd(accp[bb][o]));

    squash_epilogue<0>(tid, out);
}

// ============ ROUTED PASSES (ITER 1/2): o-split, 256-thr half-block ============
// Warp = 4 batches of this block's 32-batch half. Half-warp selects o-half.
// Pairing tree leaves lane l holding the complete agreement sum for
// o(l) = s2 ? 4 : 2*s4+s8; owners {0,8,4,12,2} hold o0..o4. Softmax via
// owner-e broadcasts + one xor16 (13 SHFL/bb).
template <int ITER>
__global__ void __launch_bounds__(NTHR, 2)
pass_kernel(const float* __restrict__ xg, const float* __restrict__ Wg,
            float* __restrict__ out)
{
    __shared__ float4 shW[3][NWITEM];
    __shared__ float4 shx[3][NXITEM];

    const int tid  = threadIdx.x;
    const int bhalf = blockIdx.x & 1;
    const int st0   = blockIdx.x >> 1;

    const int wid  = tid >> 5;        // warp 0..7
    const int l32  = tid & 31;
    const int d    = tid & 15;        // d-lane
    const int ob   = (l32 >> 4) * 5;  // o-half base: 0 or 5
    const int bl   = wid * 4;         // block-local batch base
    const int bg   = bhalf * 32 + bl; // global batch base

    const bool s8 = (d & 8) != 0;
    const bool s4 = (d & 4) != 0;
    const bool s2 = (d & 2) != 0;

    float vr[4][5], acc[4][5];
    {
        const float* vin = (ITER == 1) ? g_v : g_vsum;
        #pragma unroll
        for (int bb = 0; bb < 4; bb++)
            #pragma unroll
            for (int o = 0; o < 5; o++) {
                vr[bb][o] = vin[((bg + bb) * NO + ob + o) * ND + d];
                acc[bb][o] = 0.f;
            }
    }

    const float4* Wf4 = (const float4*)Wg;
    const float4* xf4 = (const float4*)xg;

    Stager sg;
    sg.init(tid, bhalf, st0 * ITILE, Wf4, xf4, sptr(&shW[0][0]), sptr(&shx[0][0]));

    sg.issue(0);
    if (st0 + NPAIR < NSTAGES) sg.issue(1); else cp_commit();

    int parity = 0, inext = 2;
    for (int st = st0; st < NSTAGES; st += NPAIR) {
        cp_wait<1>();
        __syncthreads();
        if (st + 2 * NPAIR < NSTAGES) sg.issue(inext); else cp_commit();
        inext = (inext + 1 == 3) ? 0 : inext + 1;

        const ulonglong2* shWc = reinterpret_cast<const ulonglong2*>(shW[parity]);
        const ulonglong2* shxc = reinterpret_cast<const ulonglong2*>(shx[parity]);

        #pragma unroll
        for (int j = 0; j < ITILE; j++) {
            ulonglong2 xa[4], xb[4];
            #pragma unroll
            for (int bb = 0; bb < 4; bb++) {
                xa[bb] = shxc[(j * 32 + bl + bb) * 2 + 0];  // e0..3
                xb[bb] = shxc[(j * 32 + bl + bb) * 2 + 1];  // e4..7
            }

            // u[bb][oo] for this half's 5 o's, 4 batches
            float u[4][5];
            #pragma unroll
            for (int oo = 0; oo < 5; oo++) {
                const int og = ob + oo;
                ulonglong2 wa = shWc[(j * NO + og) * 32 + d];
                ulonglong2 wb = shWc[(j * NO + og) * 32 + 16 + d];
                #pragma unroll
                for (int bb = 0; bb < 4; bb++) {
                    unsigned long long t = f2mul(wa.x, xa[bb].x);
                    t = f2fma(wa.y, xa[bb].y, t);
                    t = f2fma(wb.x, xb[bb].x, t);
                    t = f2fma(wb.y, xb[bb].y, t);
                    u[bb][oo] = f2hadd(t);
                }
            }

            // routing per batch: both halves handle their own 5 o's in SIMD
            #pragma unroll
            for (int bb = 0; bb < 4; bb++) {
                float p[5];
                #pragma unroll
                for (int oo = 0; oo < 5; oo++) p[oo] = u[bb][oo] * vr[bb][oo];

                // pairing tree over 16 d-lanes, 5 arrays -> 7 SHFL
                float q0, q1, q2;
                {
                    float keep = s8 ? p[1] : p[0];
                    float send = s8 ? p[0] : p[1];
                    q0 = keep + __shfl_xor_sync(0xffffffffu, send, 8, 16);
                }
                {
                    float keep = s8 ? p[3] : p[2];
                    float send = s8 ? p[2] : p[3];
                    q1 = keep + __shfl_xor_sync(0xffffffffu, send, 8, 16);
                }
                q2 = p[4] + __shfl_xor_sync(0xffffffffu, p[4], 8, 16);
                float r0, r1;
                {
                    float keep = s4 ? q1 : q0;
                    float send = s4 ? q0 : q1;
                    r0 = keep + __shfl_xor_sync(0xffffffffu, send, 4, 16);
                }
                r1 = q2 + __shfl_xor_sync(0xffffffffu, q2, 4, 16);
                float t0;
                {
                    float keep = s2 ? r1 : r0;
                    float send = s2 ? r0 : r1;
                    t0 = keep + __shfl_xor_sync(0xffffffffu, send, 2, 16);
                }
                float a = t0 + __shfl_xor_sync(0xffffffffu, t0, 1, 16);
                // lane holds complete a for o = s2 ? 4 : 2*s4+s8 (local)

                // exp at every lane (logits tiny -> no max subtraction)
                float e = __expf(a);

                // broadcast the 5 e's from owner lanes (this half's o0..o4)
                float e0 = __shfl_sync(0xffffffffu, e, 0, 16);
                float e1 = __shfl_sync(0xffffffffu, e, 8, 16);
                float e2 = __shfl_sync(0xffffffffu, e, 4, 16);
                float e3 = __shfl_sync(0xffffffffu, e, 12, 16);
                float e4 = __shfl_sync(0xffffffffu, e, 2, 16);

                // denominator: this half's sum + other half's sum (xor16)
                float mh = ((e0 + e1) + (e2 + e3)) + e4;
                float m  = mh + __shfl_xor_sync(0xffffffffu, mh, 16);
                float rinv = __fdividef(1.f, m);

                acc[bb][0] = fmaf(e0 * rinv, u[bb][0], acc[bb][0]);
                acc[bb][1] = fmaf(e1 * rinv, u[bb][1], acc[bb][1]);
                acc[bb][2] = fmaf(e2 * rinv, u[bb][2], acc[bb][2]);
                acc[bb][3] = fmaf(e3 * rinv, u[bb][3], acc[bb][3]);
                acc[bb][4] = fmaf(e4 * rinv, u[bb][4], acc[bb][4]);
            }
        }
        parity = (parity + 1 == 3) ? 0 : parity + 1;
    }

    #pragma unroll
    for (int bb = 0; bb < 4; bb++)
        #pragma unroll
        for (int oo = 0; oo < 5; oo++)
            atomicAdd(&g_s[((bg + bb) * NO + ob + oo) * ND + d], acc[bb][oo]);

    squash_epilogue<ITER>(tid, out);
}

extern "C" void kernel_launch(void* const* d_in, const int* in_sizes, int n_in,
                              void* d_out, int out_size)
{
    const float* x = (const float*)d_in[0];  // [64, 8000, 8]
    const float* W = (const float*)d_in[1];  // [10, 8000, 16, 8]
    float* out = (float*)d_out;              // [64, 10, 16]

    pass0_kernel<<<NBLK, NTHR>>>(x, W, out);    // uniform c=0.1 (in prescale)
    pass_kernel<1><<<NBLK, NTHR>>>(x, W, out);  // c = softmax_o(u.v0)
    pass_kernel<2><<<NBLK, NTHR>>>(x, W, out);  // c = softmax_o(u.(v0+v1))
}

// round 14
// speedup vs baseline: 1.1408x; 1.1408x over previous
#include <cuda_runtime.h>
#include <cstdint>

#define NB 64
#define NO 10
#define NI 8000
#define ND 16
#define NE 8

#define ITILE 4
#define NTHR 512
#define NSTAGES (NI / ITILE)     // 2000 stages of 4 i's

#define NWITEM (ITILE * NO * 32) // 1280 W float4 per stage
#define NXITEM (ITILE * NB * 2)  // 512 x float4 per stage
#define WBUFB (NWITEM * 16)      // 20480 B per W buffer
#define XBUFB (NXITEM * 16)      // 8192 B per x buffer
#define SMEM_BYTES (3 * (WBUFB + XBUFB))  // 86016 B dynamic

#define NBLK 148                 // 1 block/SM, one full wave
#define STEPI (NBLK * ITILE)     // i0 advance per grid-stride step = 592

// Scratch (no allocation allowed). g_s zeroed by the fused squash each pass,
// g_ticket reset by the last block -> graph replays are deterministic.
__device__ float g_s[NB * NO * ND] = {};
__device__ float g_v[NB * NO * ND] = {};
__device__ float g_vsum[NB * NO * ND] = {};
__device__ unsigned int g_ticket = 0;

// ---- f32x2 packed math (sm_10x; ptxas won't auto-fuse, must be PTX) ----
__device__ __forceinline__ unsigned long long f2mul(unsigned long long a, unsigned long long b) {
    unsigned long long d;
    asm("mul.rn.f32x2 %0, %1, %2;" : "=l"(d) : "l"(a), "l"(b));
    return d;
}
__device__ __forceinline__ unsigned long long f2fma(unsigned long long a, unsigned long long b, unsigned long long c) {
    unsigned long long d;
    asm("fma.rn.f32x2 %0, %1, %2, %3;" : "=l"(d) : "l"(a), "l"(b), "l"(c));
    return d;
}
__device__ __forceinline__ float f2hadd(unsigned long long a) {
    float lo, hi;
    asm("mov.b64 {%0, %1}, %2;" : "=f"(lo), "=f"(hi) : "l"(a));
    return lo + hi;
}

// ---- cp.async (LDGSTS) helpers ----
__device__ __forceinline__ void cp16(uint32_t dst, const void* src) {
    asm volatile("cp.async.ca.shared.global [%0], [%1], 16;" :: "r"(dst), "l"(src));
}
__device__ __forceinline__ void cp_commit() { asm volatile("cp.async.commit_group;"); }
template <int N>
__device__ __forceinline__ void cp_wait() { asm volatile("cp.async.wait_group %0;" :: "n"(N)); }
__device__ __forceinline__ uint32_t sptr(const void* p) {
    return (uint32_t)__cvta_generic_to_shared(p);
}

// ---- staging: 1792 items (1280 W + 512 x), 512 threads -> 3-4 cp16 each ----
// cpA: W item tid. cpB: W item tid+512.
// cpC: tid<256 -> W item tid+1024, else x item tid-256.
// cpD: tid<256 -> x item tid+256.
// shW per (j,o): 32 float4, idx qs = e4*16 + d. shx per (j,b): 2 float4.
struct Stager {
    const float4 *sA, *sB, *sC, *sD;
    uint32_t dA, dB, dC, dD, bufC;
    int stC;
    bool hasD;

    __device__ __forceinline__ void initW(int t, int i00, const float4* Wf4,
                                          uint32_t swbase,
                                          const float4*& src, uint32_t& dst) {
        int j  = t / (NO * 32);
        int r  = t - j * (NO * 32);
        int o  = r >> 5;
        int qg = r & 31;                       // global: d*2 + e4
        int qs = ((qg & 1) << 4) | (qg >> 1);  // shared: e4*16 + d
        src = Wf4 + ((size_t)o * NI + i00 + j) * 32 + qg;
        dst = swbase + (uint32_t)((j * NO + o) * 32 + qs) * 16u;
    }
    __device__ __forceinline__ void initX(int v, int i00, const float4* xf4,
                                          uint32_t sxbase,
                                          const float4*& src, uint32_t& dst) {
        int j = v >> 7;
        int r = v & 127;
        int b = r >> 1;
        int q = r & 1;
        src = xf4 + ((size_t)b * NI + i00 + j) * 2 + q;
        dst = sxbase + (uint32_t)((j * NB + b) * 2 + q) * 16u;
    }

    __device__ __forceinline__ void init(int tid, int i00,
                                         const float4* Wf4, const float4* xf4,
                                         uint32_t swbase, uint32_t sxbase) {
        initW(tid,       i00, Wf4, swbase, sA, dA);
        initW(tid + 512, i00, Wf4, swbase, sB, dB);
        hasD = (tid < 256);
        if (hasD) {
            initW(tid + 1024, i00, Wf4, swbase, sC, dC);
            stC = 32 * STEPI; bufC = WBUFB;
            initX(tid + 256, i00, xf4, sxbase, sD, dD);
        } else {
            initX(tid - 256, i00, xf4, sxbase, sC, dC);
            stC = 2 * STEPI; bufC = XBUFB;
            sD = xf4; dD = sxbase;
        }
    }
    __device__ __forceinline__ void issue(int ib) {
        cp16(dA + (uint32_t)ib * WBUFB, sA);  sA += 32 * STEPI;
        cp16(dB + (uint32_t)ib * WBUFB, sB);  sB += 32 * STEPI;
        cp16(dC + (uint32_t)ib * bufC,  sC);  sC += stC;
        if (hasD) { cp16(dD + (uint32_t)ib * XBUFB, sD); sD += 2 * STEPI; }
        cp_commit();
    }
};

// ---- fused squash epilogue (last block), shared by all passes ----
template <int ITER>
__device__ __forceinline__ void squash_epilogue(int tid, float* __restrict__ out)
{
    __threadfence();
    __shared__ unsigned int lastFlag;
    if (tid == 0)
        lastFlag = (atomicAdd(&g_ticket, 1u) == (unsigned)(NBLK - 1)) ? 1u : 0u;
    __syncthreads();
    if (!lastFlag) return;
    __threadfence();  // acquire: all other blocks' atomics are visible

    const float prescale = (ITER == 0) ? 0.1f : 1.0f;
    #pragma unroll
    for (int k = 0; k < (NB * NO * ND) / NTHR; k++) {
        int idx = k * NTHR + tid;            // idx & 15 == d-lane
        float val = g_s[idx] * prescale;
        g_s[idx] = 0.f;
        float n2 = val * val;
        n2 += __shfl_xor_sync(0xffffffffu, n2, 8, 16);
        n2 += __shfl_xor_sync(0xffffffffu, n2, 4, 16);
        n2 += __shfl_xor_sync(0xffffffffu, n2, 2, 16);
        n2 += __shfl_xor_sync(0xffffffffu, n2, 1, 16);
        float norm  = sqrtf(n2);
        float scale = n2 / ((1.f + n2) * (norm + 1e-8f));
        float v = scale * val;
        if (ITER == 0)      { g_v[idx] = v; g_vsum[idx] = v; }
        else if (ITER == 1) { g_v[idx] = v; g_vsum[idx] += v; }
        else                { out[idx] = v; }
    }
    if (tid == 0) g_ticket = 0;  // reset for next pass / next graph replay
}

// ============ PASS 0: (4 batch, 5 o) per thread ============
__global__ void __launch_bounds__(NTHR, 1)
pass0_kernel(const float* __restrict__ xg, const float* __restrict__ Wg,
             float* __restrict__ out)
{
    extern __shared__ float4 smem[];          // [3*NWITEM W | 3*NXITEM x]
    float4* shW = smem;
    float4* shx = smem + 3 * NWITEM;

    const int tid  = threadIdx.x;
    const int lane = tid & 15;        // d
    const int grp  = tid >> 4;        // 0..31
    const int quad = grp >> 1;        // 0..15 -> batches 4q..4q+3
    const int ob   = (grp & 1) * 5;   // o-half base: 0 or 5

    unsigned long long accp[4][5];
    #pragma unroll
    for (int bb = 0; bb < 4; bb++)
        #pragma unroll
        for (int o = 0; o < 5; o++) accp[bb][o] = 0ull;

    const float4* Wf4 = (const float4*)Wg;
    const float4* xf4 = (const float4*)xg;

    Stager sg;
    sg.init(tid, blockIdx.x * ITILE, Wf4, xf4, sptr(shW), sptr(shx));

    const int st0 = blockIdx.x;
    sg.issue(0);
    if (st0 + NBLK < NSTAGES) sg.issue(1); else cp_commit();

    int parity = 0, inext = 2;
    for (int st = st0; st < NSTAGES; st += NBLK) {
        cp_wait<1>();
        __syncthreads();
        if (st + 2 * NBLK < NSTAGES) sg.issue(inext); else cp_commit();
        inext = (inext + 1 == 3) ? 0 : inext + 1;

        const ulonglong2* shWc = reinterpret_cast<const ulonglong2*>(shW + parity * NWITEM);
        const ulonglong2* shxc = reinterpret_cast<const ulonglong2*>(shx + parity * NXITEM);

        #pragma unroll
        for (int j = 0; j < ITILE; j++) {
            ulonglong2 xa[4], xb[4];
            #pragma unroll
            for (int bb = 0; bb < 4; bb++) {
                xa[bb] = shxc[(j * NB + quad * 4 + bb) * 2 + 0];  // e0..3
                xb[bb] = shxc[(j * NB + quad * 4 + bb) * 2 + 1];  // e4..7
            }
            #pragma unroll
            for (int o = 0; o < 5; o++) {
                const int og = ob + o;
                ulonglong2 wa = shWc[(j * NO + og) * 32 + lane];       // e0..3
                ulonglong2 wb = shWc[(j * NO + og) * 32 + 16 + lane];  // e4..7
                #pragma unroll
                for (int bb = 0; bb < 4; bb++) {
                    accp[bb][o] = f2fma(wa.x, xa[bb].x, accp[bb][o]);
                    accp[bb][o] = f2fma(wa.y, xa[bb].y, accp[bb][o]);
                    accp[bb][o] = f2fma(wb.x, xb[bb].x, accp[bb][o]);
                    accp[bb][o] = f2fma(wb.y, xb[bb].y, accp[bb][o]);
                }
            }
        }
        parity = (parity + 1 == 3) ? 0 : parity + 1;
    }

    #pragma unroll
    for (int bb = 0; bb < 4; bb++)
        #pragma unroll
        for (int o = 0; o < 5; o++)
            atomicAdd(&g_s[((quad * 4 + bb) * NO + ob + o) * ND + lane],
                      f2hadd(accp[bb][o]));

    squash_epilogue<0>(tid, out);
}

// ============ ROUTED PASSES (ITER 1/2): o-split + e-broadcast softmax ============
// Warp = 4 batches. Half-warp selects o-half: lanes 0-15 -> o in [0,5),
// lanes 16-31 -> o in [5,10); d = lane & 15. Pairing tree leaves lane l
// holding the complete agreement sum for o(l) = s2 ? 4 : 2*s4+s8; owners
// {0,8,4,12,2} hold o0..o4. Softmax via owner-e broadcasts + one xor16.
template <int ITER>
__global__ void __launch_bounds__(NTHR, 1)
pass_kernel(const float* __restrict__ xg, const float* __restrict__ Wg,
            float* __restrict__ out)
{
    extern __shared__ float4 smem[];
    float4* shW = smem;
    float4* shx = smem + 3 * NWITEM;

    const int tid  = threadIdx.x;
    const int wid  = tid >> 5;        // warp 0..15
    const int l32  = tid & 31;
    const int d    = tid & 15;        // d-lane
    const int ob   = (l32 >> 4) * 5;  // o-half base: 0 or 5
    const int bq   = wid * 4;         // batch base

    const bool s8 = (d & 8) != 0;
    const bool s4 = (d & 4) != 0;
    const bool s2 = (d & 2) != 0;

    float vr[4][5], acc[4][5];
    {
        const float* vin = (ITER == 1) ? g_v : g_vsum;
        #pragma unroll
        for (int bb = 0; bb < 4; bb++)
            #pragma unroll
            for (int o = 0; o < 5; o++) {
                vr[bb][o] = vin[((bq + bb) * NO + ob + o) * ND + d];
                acc[bb][o] = 0.f;
            }
    }

    const float4* Wf4 = (const float4*)Wg;
    const float4* xf4 = (const float4*)xg;

    Stager sg;
    sg.init(tid, blockIdx.x * ITILE, Wf4, xf4, sptr(shW), sptr(shx));

    const int st0 = blockIdx.x;
    sg.issue(0);
    if (st0 + NBLK < NSTAGES) sg.issue(1); else cp_commit();

    int parity = 0, inext = 2;
    for (int st = st0; st < NSTAGES; st += NBLK) {
        cp_wait<1>();
        __syncthreads();
        if (st + 2 * NBLK < NSTAGES) sg.issue(inext); else cp_commit();
        inext = (inext + 1 == 3) ? 0 : inext + 1;

        const ulonglong2* shWc = reinterpret_cast<const ulonglong2*>(shW + parity * NWITEM);
        const ulonglong2* shxc = reinterpret_cast<const ulonglong2*>(shx + parity * NXITEM);

        #pragma unroll
        for (int j = 0; j < ITILE; j++) {
            ulonglong2 xa[4], xb[4];
            #pragma unroll
            for (int bb = 0; bb < 4; bb++) {
                xa[bb] = shxc[(j * NB + bq + bb) * 2 + 0];  // e0..3
                xb[bb] = shxc[(j * NB + bq + bb) * 2 + 1];  // e4..7
            }

            // u[bb][oo] for this half's 5 o's, 4 batches
            float u[4][5];
            #pragma unroll
            for (int oo = 0; oo < 5; oo++) {
                const int og = ob + oo;
                ulonglong2 wa = shWc[(j * NO + og) * 32 + d];
                ulonglong2 wb = shWc[(j * NO + og) * 32 + 16 + d];
                #pragma unroll
                for (int bb = 0; bb < 4; bb++) {
                    unsigned long long t = f2mul(wa.x, xa[bb].x);
                    t = f2fma(wa.y, xa[bb].y, t);
                    t = f2fma(wb.x, xb[bb].x, t);
                    t = f2fma(wb.y, xb[bb].y, t);
                    u[bb][oo] = f2hadd(t);
                }
            }

            // routing per batch: both halves handle their own 5 o's in SIMD
            #pragma unroll
            for (int bb = 0; bb < 4; bb++) {
                float p[5];
                #pragma unroll
                for (int oo = 0; oo < 5; oo++) p[oo] = u[bb][oo] * vr[bb][oo];

                // pairing tree over 16 d-lanes, 5 arrays -> 7 SHFL
                float q0, q1, q2;
                {
                    float keep = s8 ? p[1] : p[0];
                    float send = s8 ? p[0] : p[1];
                    q0 = keep + __shfl_xor_sync(0xffffffffu, send, 8, 16);
                }
                {
                    float keep = s8 ? p[3] : p[2];
                    float send = s8 ? p[2] : p[3];
                    q1 = keep + __shfl_xor_sync(0xffffffffu, send, 8, 16);
                }
                q2 = p[4] + __shfl_xor_sync(0xffffffffu, p[4], 8, 16);
                float r0, r1;
                {
                    float keep = s4 ? q1 : q0;
                    float send = s4 ? q0 : q1;
                    r0 = keep + __shfl_xor_sync(0xffffffffu, send, 4, 16);
                }
                r1 = q2 + __shfl_xor_sync(0xffffffffu, q2, 4, 16);
                float t0;
                {
                    float keep = s2 ? r1 : r0;
                    float send = s2 ? r0 : r1;
                    t0 = keep + __shfl_xor_sync(0xffffffffu, send, 2, 16);
                }
                float a = t0 + __shfl_xor_sync(0xffffffffu, t0, 1, 16);
                // lane holds complete a for o = s2 ? 4 : 2*s4+s8 (local)

                // exp at every lane (logits tiny -> no max subtraction)
                float e = __expf(a);

                // broadcast the 5 e's from owner lanes (this half's o0..o4)
                float e0 = __shfl_sync(0xffffffffu, e, 0, 16);
                float e1 = __shfl_sync(0xffffffffu, e, 8, 16);
                float e2 = __shfl_sync(0xffffffffu, e, 4, 16);
                float e3 = __shfl_sync(0xffffffffu, e, 12, 16);
                float e4 = __shfl_sync(0xffffffffu, e, 2, 16);

                // denominator: this half's sum + other half's sum (xor16)
                float mh = ((e0 + e1) + (e2 + e3)) + e4;
                float m  = mh + __shfl_xor_sync(0xffffffffu, mh, 16);
                float rinv = __fdividef(1.f, m);

                acc[bb][0] = fmaf(e0 * rinv, u[bb][0], acc[bb][0]);
                acc[bb][1] = fmaf(e1 * rinv, u[bb][1], acc[bb][1]);
                acc[bb][2] = fmaf(e2 * rinv, u[bb][2], acc[bb][2]);
                acc[bb][3] = fmaf(e3 * rinv, u[bb][3], acc[bb][3]);
                acc[bb][4] = fmaf(e4 * rinv, u[bb][4], acc[bb][4]);
            }
        }
        parity = (parity + 1 == 3) ? 0 : parity + 1;
    }

    #pragma unroll
    for (int bb = 0; bb < 4; bb++)
        #pragma unroll
        for (int oo = 0; oo < 5; oo++)
            atomicAdd(&g_s[((bq + bb) * NO + ob + oo) * ND + d], acc[bb][oo]);

    squash_epilogue<ITER>(tid, out);
}

extern "C" void kernel_launch(void* const* d_in, const int* in_sizes, int n_in,
                              void* d_out, int out_size)
{
    const float* x = (const float*)d_in[0];  // [64, 8000, 8]
    const float* W = (const float*)d_in[1];  // [10, 8000, 16, 8]
    float* out = (float*)d_out;              // [64, 10, 16]

    // dynamic smem opt-in (host attribute set; idempotent, capture-safe)
    cudaFuncSetAttribute(pass0_kernel,
                         cudaFuncAttributeMaxDynamicSharedMemorySize, SMEM_BYTES);
    cudaFuncSetAttribute(pass_kernel<1>,
                         cudaFuncAttributeMaxDynamicSharedMemorySize, SMEM_BYTES);
    cudaFuncSetAttribute(pass_kernel<2>,
                         cudaFuncAttributeMaxDynamicSharedMemorySize, SMEM_BYTES);

    pass0_kernel<<<NBLK, NTHR, SMEM_BYTES>>>(x, W, out);
    pass_kernel<1><<<NBLK, NTHR, SMEM_BYTES>>>(x, W, out);
    pass_kernel<2><<<NBLK, NTHR, SMEM_BYTES>>>(x, W, out);
}

// round 15
// speedup vs baseline: 1.1439x; 1.0027x over previous
#include <cuda_runtime.h>
#include <cstdint>

#define NB 64
#define NO 10
#define NI 8000
#define ND 16
#define NE 8

#define ITILE 4
#define NTHR 512
#define NSTAGES (NI / ITILE)     // 2000 stages of 4 i's

#define NWITEM (ITILE * NO * 32) // 1280 W float4 per stage
#define NXITEM (ITILE * NB * 2)  // 512 x float4 per stage
#define WBUFB (NWITEM * 16)      // 20480 B per W buffer
#define XBUFB (NXITEM * 16)      // 8192 B per x buffer
#define SMEM_BYTES (3 * (WBUFB + XBUFB))  // 86016 B dynamic

#define NBLK 148                 // 1 block/SM, one full wave
#define STEPI (NBLK * ITILE)     // i0 advance per grid-stride step = 592

// Scratch (no allocation allowed). g_s zeroed by the fused squash each pass,
// g_ticket reset by the last block -> graph replays are deterministic.
__device__ float g_s[NB * NO * ND] = {};
__device__ float g_v[NB * NO * ND] = {};
__device__ float g_vsum[NB * NO * ND] = {};
__device__ unsigned int g_ticket = 0;

// ---- f32x2 packed math (sm_10x; ptxas won't auto-fuse, must be PTX) ----
__device__ __forceinline__ unsigned long long f2mul(unsigned long long a, unsigned long long b) {
    unsigned long long d;
    asm("mul.rn.f32x2 %0, %1, %2;" : "=l"(d) : "l"(a), "l"(b));
    return d;
}
__device__ __forceinline__ unsigned long long f2fma(unsigned long long a, unsigned long long b, unsigned long long c) {
    unsigned long long d;
    asm("fma.rn.f32x2 %0, %1, %2, %3;" : "=l"(d) : "l"(a), "l"(b), "l"(c));
    return d;
}
__device__ __forceinline__ float f2hadd(unsigned long long a) {
    float lo, hi;
    asm("mov.b64 {%0, %1}, %2;" : "=f"(lo), "=f"(hi) : "l"(a));
    return lo + hi;
}

// ---- cp.async (LDGSTS) helpers ----
__device__ __forceinline__ void cp16(uint32_t dst, const void* src) {
    asm volatile("cp.async.ca.shared.global [%0], [%1], 16;" :: "r"(dst), "l"(src));
}
__device__ __forceinline__ void cp_commit() { asm volatile("cp.async.commit_group;"); }
template <int N>
__device__ __forceinline__ void cp_wait() { asm volatile("cp.async.wait_group %0;" :: "n"(N)); }
__device__ __forceinline__ uint32_t sptr(const void* p) {
    return (uint32_t)__cvta_generic_to_shared(p);
}

// ---- staging: 1792 items (1280 W + 512 x), 512 threads -> 3-4 cp16 each ----
// cpA: W item tid. cpB: W item tid+512.
// cpC: tid<256 -> W item tid+1024, else x item tid-256.
// cpD: tid<256 -> x item tid+256.
// shW per (j,o): 32 float4, idx qs = e4*16 + d. shx per (j,b): 2 float4.
struct Stager {
    const float4 *sA, *sB, *sC, *sD;
    uint32_t dA, dB, dC, dD, bufC;
    int stC;
    bool hasD;

    __device__ __forceinline__ void initW(int t, int i00, const float4* Wf4,
                                          uint32_t swbase,
                                          const float4*& src, uint32_t& dst) {
        int j  = t / (NO * 32);
        int r  = t - j * (NO * 32);
        int o  = r >> 5;
        int qg = r & 31;                       // global: d*2 + e4
        int qs = ((qg & 1) << 4) | (qg >> 1);  // shared: e4*16 + d
        src = Wf4 + ((size_t)o * NI + i00 + j) * 32 + qg;
        dst = swbase + (uint32_t)((j * NO + o) * 32 + qs) * 16u;
    }
    __device__ __forceinline__ void initX(int v, int i00, const float4* xf4,
                                          uint32_t sxbase,
                                          const float4*& src, uint32_t& dst) {
        int j = v >> 7;
        int r = v & 127;
        int b = r >> 1;
        int q = r & 1;
        src = xf4 + ((size_t)b * NI + i00 + j) * 2 + q;
        dst = sxbase + (uint32_t)((j * NB + b) * 2 + q) * 16u;
    }

    __device__ __forceinline__ void init(int tid, int i00,
                                         const float4* Wf4, const float4* xf4,
                                         uint32_t swbase, uint32_t sxbase) {
        initW(tid,       i00, Wf4, swbase, sA, dA);
        initW(tid + 512, i00, Wf4, swbase, sB, dB);
        hasD = (tid < 256);
        if (hasD) {
            initW(tid + 1024, i00, Wf4, swbase, sC, dC);
            stC = 32 * STEPI; bufC = WBUFB;
            initX(tid + 256, i00, xf4, sxbase, sD, dD);
        } else {
            initX(tid - 256, i00, xf4, sxbase, sC, dC);
            stC = 2 * STEPI; bufC = XBUFB;
            sD = xf4; dD = sxbase;
        }
    }
    __device__ __forceinline__ void issue(int ib) {
        cp16(dA + (uint32_t)ib * WBUFB, sA);  sA += 32 * STEPI;
        cp16(dB + (uint32_t)ib * WBUFB, sB);  sB += 32 * STEPI;
        cp16(dC + (uint32_t)ib * bufC,  sC);  sC += stC;
        if (hasD) { cp16(dD + (uint32_t)ib * XBUFB, sD); sD += 2 * STEPI; }
        cp_commit();
    }
};

// ---- fused squash epilogue (last block), shared by all passes ----
template <int ITER>
__device__ __forceinline__ void squash_epilogue(int tid, float* __restrict__ out)
{
    __threadfence();
    __shared__ unsigned int lastFlag;
    if (tid == 0)
        lastFlag = (atomicAdd(&g_ticket, 1u) == (unsigned)(NBLK - 1)) ? 1u : 0u;
    __syncthreads();
    if (!lastFlag) return;
    __threadfence();  // acquire: all other blocks' atomics are visible

    const float prescale = (ITER == 0) ? 0.1f : 1.0f;
    #pragma unroll
    for (int k = 0; k < (NB * NO * ND) / NTHR; k++) {
        int idx = k * NTHR + tid;            // idx & 15 == d-lane
        float val = g_s[idx] * prescale;
        g_s[idx] = 0.f;
        float n2 = val * val;
        n2 += __shfl_xor_sync(0xffffffffu, n2, 8, 16);
        n2 += __shfl_xor_sync(0xffffffffu, n2, 4, 16);
        n2 += __shfl_xor_sync(0xffffffffu, n2, 2, 16);
        n2 += __shfl_xor_sync(0xffffffffu, n2, 1, 16);
        float norm  = sqrtf(n2);
        float scale = n2 / ((1.f + n2) * (norm + 1e-8f));
        float v = scale * val;
        if (ITER == 0)      { g_v[idx] = v; g_vsum[idx] = v; }
        else if (ITER == 1) { g_v[idx] = v; g_vsum[idx] += v; }
        else                { out[idx] = v; }
    }
    if (tid == 0) g_ticket = 0;  // reset for next pass / next graph replay
}

// ============ PASS 0: (4 batch, 5 o) per thread ============
__global__ void __launch_bounds__(NTHR, 1)
pass0_kernel(const float* __restrict__ xg, const float* __restrict__ Wg,
             float* __restrict__ out)
{
    extern __shared__ float4 smem[];          // [3*NWITEM W | 3*NXITEM x]
    float4* shW = smem;
    float4* shx = smem + 3 * NWITEM;

    const int tid  = threadIdx.x;
    const int lane = tid & 15;        // d
    const int grp  = tid >> 4;        // 0..31
    const int quad = grp >> 1;        // 0..15 -> batches 4q..4q+3
    const int ob   = (grp & 1) * 5;   // o-half base: 0 or 5

    unsigned long long accp[4][5];
    #pragma unroll
    for (int bb = 0; bb < 4; bb++)
        #pragma unroll
        for (int o = 0; o < 5; o++) accp[bb][o] = 0ull;

    const float4* Wf4 = (const float4*)Wg;
    const float4* xf4 = (const float4*)xg;

    Stager sg;
    sg.init(tid, blockIdx.x * ITILE, Wf4, xf4, sptr(shW), sptr(shx));

    const int st0 = blockIdx.x;
    sg.issue(0);
    if (st0 + NBLK < NSTAGES) sg.issue(1); else cp_commit();

    int parity = 0, inext = 2;
    for (int st = st0; st < NSTAGES; st += NBLK) {
        cp_wait<1>();
        __syncthreads();
        if (st + 2 * NBLK < NSTAGES) sg.issue(inext); else cp_commit();
        inext = (inext + 1 == 3) ? 0 : inext + 1;

        const ulonglong2* shWc = reinterpret_cast<const ulonglong2*>(shW + parity * NWITEM);
        const ulonglong2* shxc = reinterpret_cast<const ulonglong2*>(shx + parity * NXITEM);

        #pragma unroll
        for (int j = 0; j < ITILE; j++) {
            ulonglong2 xa[4], xb[4];
            #pragma unroll
            for (int bb = 0; bb < 4; bb++) {
                xa[bb] = shxc[(j * NB + quad * 4 + bb) * 2 + 0];  // e0..3
                xb[bb] = shxc[(j * NB + quad * 4 + bb) * 2 + 1];  // e4..7
            }
            #pragma unroll
            for (int o = 0; o < 5; o++) {
                const int og = ob + o;
                ulonglong2 wa = shWc[(j * NO + og) * 32 + lane];       // e0..3
                ulonglong2 wb = shWc[(j * NO + og) * 32 + 16 + lane];  // e4..7
                #pragma unroll
                for (int bb = 0; bb < 4; bb++) {
                    accp[bb][o] = f2fma(wa.x, xa[bb].x, accp[bb][o]);
                    accp[bb][o] = f2fma(wa.y, xa[bb].y, accp[bb][o]);
                    accp[bb][o] = f2fma(wb.x, xb[bb].x, accp[bb][o]);
                    accp[bb][o] = f2fma(wb.y, xb[bb].y, accp[bb][o]);
                }
            }
        }
        parity = (parity + 1 == 3) ? 0 : parity + 1;
    }

    #pragma unroll
    for (int bb = 0; bb < 4; bb++)
        #pragma unroll
        for (int o = 0; o < 5; o++)
            atomicAdd(&g_s[((quad * 4 + bb) * NO + ob + o) * ND + lane],
                      f2hadd(accp[bb][o]));

    squash_epilogue<0>(tid, out);
}

// ============ ROUTED PASSES (ITER 1/2): o-split + e-broadcast softmax ============
// Warp = 4 batches. Half-warp selects o-half: lanes 0-15 -> o in [0,5),
// lanes 16-31 -> o in [5,10); d = lane & 15. Pairing tree leaves lane l
// holding the complete agreement sum for o(l) = s2 ? 4 : 2*s4+s8; owners
// {0,8,4,12,2} hold o0..o4. Softmax via owner-e broadcasts + one xor16.
template <int ITER>
__global__ void __launch_bounds__(NTHR, 1)
pass_kernel(const float* __restrict__ xg, const float* __restrict__ Wg,
            float* __restrict__ out)
{
    extern __shared__ float4 smem[];
    float4* shW = smem;
    float4* shx = smem + 3 * NWITEM;

    const int tid  = threadIdx.x;
    const int wid  = tid >> 5;        // warp 0..15
    const int l32  = tid & 31;
    const int d    = tid & 15;        // d-lane
    const int ob   = (l32 >> 4) * 5;  // o-half base: 0 or 5
    const int bq   = wid * 4;         // batch base

    const bool s8 = (d & 8) != 0;
    const bool s4 = (d & 4) != 0;
    const bool s2 = (d & 2) != 0;

    float vr[4][5], acc[4][5];
    {
        const float* vin = (ITER == 1) ? g_v : g_vsum;
        #pragma unroll
        for (int bb = 0; bb < 4; bb++)
            #pragma unroll
            for (int o = 0; o < 5; o++) {
                vr[bb][o] = vin[((bq + bb) * NO + ob + o) * ND + d];
                acc[bb][o] = 0.f;
            }
    }

    const float4* Wf4 = (const float4*)Wg;
    const float4* xf4 = (const float4*)xg;

    Stager sg;
    sg.init(tid, blockIdx.x * ITILE, Wf4, xf4, sptr(shW), sptr(shx));

    const int st0 = blockIdx.x;
    sg.issue(0);
    if (st0 + NBLK < NSTAGES) sg.issue(1); else cp_commit();

    int parity = 0, inext = 2;
    for (int st = st0; st < NSTAGES; st += NBLK) {
        cp_wait<1>();
        __syncthreads();
        if (st + 2 * NBLK < NSTAGES) sg.issue(inext); else cp_commit();
        inext = (inext + 1 == 3) ? 0 : inext + 1;

        const ulonglong2* shWc = reinterpret_cast<const ulonglong2*>(shW + parity * NWITEM);
        const ulonglong2* shxc = reinterpret_cast<const ulonglong2*>(shx + parity * NXITEM);

        #pragma unroll
        for (int j = 0; j < ITILE; j++) {
            ulonglong2 xa[4], xb[4];
            #pragma unroll
            for (int bb = 0; bb < 4; bb++) {
                xa[bb] = shxc[(j * NB + bq + bb) * 2 + 0];  // e0..3
                xb[bb] = shxc[(j * NB + bq + bb) * 2 + 1];  // e4..7
            }

            // u[bb][oo] for this half's 5 o's, 4 batches
            float u[4][5];
            #pragma unroll
            for (int oo = 0; oo < 5; oo++) {
                const int og = ob + oo;
                ulonglong2 wa = shWc[(j * NO + og) * 32 + d];
                ulonglong2 wb = shWc[(j * NO + og) * 32 + 16 + d];
                #pragma unroll
                for (int bb = 0; bb < 4; bb++) {
                    unsigned long long t = f2mul(wa.x, xa[bb].x);
                    t = f2fma(wa.y, xa[bb].y, t);
                    t = f2fma(wb.x, xb[bb].x, t);
                    t = f2fma(wb.y, xb[bb].y, t);
                    u[bb][oo] = f2hadd(t);
                }
            }

            // routing per batch: both halves handle their own 5 o's in SIMD
            #pragma unroll
            for (int bb = 0; bb < 4; bb++) {
                float p[5];
                #pragma unroll
                for (int oo = 0; oo < 5; oo++) p[oo] = u[bb][oo] * vr[bb][oo];

                // pairing tree over 16 d-lanes, 5 arrays -> 7 SHFL
                float q0, q1, q2;
                {
                    float keep = s8 ? p[1] : p[0];
                    float send = s8 ? p[0] : p[1];
                    q0 = keep + __shfl_xor_sync(0xffffffffu, send, 8, 16);
                }
                {
                    float keep = s8 ? p[3] : p[2];
                    float send = s8 ? p[2] : p[3];
                    q1 = keep + __shfl_xor_sync(0xffffffffu, send, 8, 16);
                }
                q2 = p[4] + __shfl_xor_sync(0xffffffffu, p[4], 8, 16);
                float r0, r1;
                {
                    float keep = s4 ? q1 : q0;
                    float send = s4 ? q0 : q1;
                    r0 = keep + __shfl_xor_sync(0xffffffffu, send, 4, 16);
                }
                r1 = q2 + __shfl_xor_sync(0xffffffffu, q2, 4, 16);
                float t0;
                {
                    float keep = s2 ? r1 : r0;
                    float send = s2 ? r0 : r1;
                    t0 = keep + __shfl_xor_sync(0xffffffffu, send, 2, 16);
                }
                float a = t0 + __shfl_xor_sync(0xffffffffu, t0, 1, 16);
                // lane holds complete a for o = s2 ? 4 : 2*s4+s8 (local)

                // exp at every lane (logits tiny -> no max subtraction)
                float e = __expf(a);

                // broadcast the 5 e's from owner lanes (this half's o0..o4)
                float e0 = __shfl_sync(0xffffffffu, e, 0, 16);
                float e1 = __shfl_sync(0xffffffffu, e, 8, 16);
                float e2 = __shfl_sync(0xffffffffu, e, 4, 16);
                float e3 = __shfl_sync(0xffffffffu, e, 12, 16);
                float e4 = __shfl_sync(0xffffffffu, e, 2, 16);

                // denominator: this half's sum + other half's sum (xor16)
                float mh = ((e0 + e1) + (e2 + e3)) + e4;
                float m  = mh + __shfl_xor_sync(0xffffffffu, mh, 16);
                float rinv = __fdividef(1.f, m);

                acc[bb][0] = fmaf(e0 * rinv, u[bb][0], acc[bb][0]);
                acc[bb][1] = fmaf(e1 * rinv, u[bb][1], acc[bb][1]);
                acc[bb][2] = fmaf(e2 * rinv, u[bb][2], acc[bb][2]);
                acc[bb][3] = fmaf(e3 * rinv, u[bb][3], acc[bb][3]);
                acc[bb][4] = fmaf(e4 * rinv, u[bb][4], acc[bb][4]);
            }
        }
        parity = (parity + 1 == 3) ? 0 : parity + 1;
    }

    #pragma unroll
    for (int bb = 0; bb < 4; bb++)
        #pragma unroll
        for (int oo = 0; oo < 5; oo++)
            atomicAdd(&g_s[((bq + bb) * NO + ob + oo) * ND + d], acc[bb][oo]);

    squash_epilogue<ITER>(tid, out);
}

extern "C" void kernel_launch(void* const* d_in, const int* in_sizes, int n_in,
                              void* d_out, int out_size)
{
    const float* x = (const float*)d_in[0];  // [64, 8000, 8]
    const float* W = (const float*)d_in[1];  // [10, 8000, 16, 8]
    float* out = (float*)d_out;              // [64, 10, 16]

    // dynamic smem opt-in (host attribute set; idempotent, capture-safe)
    cudaFuncSetAttribute(pass0_kernel,
                         cudaFuncAttributeMaxDynamicSharedMemorySize, SMEM_BYTES);
    cudaFuncSetAttribute(pass_kernel<1>,
                         cudaFuncAttributeMaxDynamicSharedMemorySize, SMEM_BYTES);
    cudaFuncSetAttribute(pass_kernel<2>,
                         cudaFuncAttributeMaxDynamicSharedMemorySize, SMEM_BYTES);

    pass0_kernel<<<NBLK, NTHR, SMEM_BYTES>>>(x, W, out);
    pass_kernel<1><<<NBLK, NTHR, SMEM_BYTES>>>(x, W, out);
    pass_kernel<2><<<NBLK, NTHR, SMEM_BYTES>>>(x, W, out);
}